// round 16
// baseline (speedup 1.0000x reference)
#include <cuda_runtime.h>
#include <cuda_fp16.h>
#include <math.h>

#define DD   1024
#define BB   16
#define TT   2048
#define NROW (TT*BB)          /* 32768 */
#define BD   (BB*DD)          /* 16384 */
#define SNB  64               /* scan blocks total (512 thr each) */
#define GRP  4                /* independent batch groups (4 batches each) */
#define BPG  16               /* blocks per group */

/* ------------- static device scratch (no allocations allowed) ------------- */
__device__ float    g_A[33554432];            /* x@Wx^T + b, [T*B, D], 128MB */
__device__ float    g_scale;                  /* 0.99/(sigma+eps) */
__device__ unsigned g_cnt4[GRP * 32];         /* one 128B line per group */
__device__ __half   g_Wh16[DD * DD];          /* fp16 of (scale * W_h), 2MB */
__device__ __half   g_h16[(TT + 1) * BD];     /* fp16 shadow of h, 67MB */
__device__ float    g_u[DD];
__device__ float    g_v[DD];
__device__ float    g_part[16][DD];

/* ====================== small PTX helpers ================================ */
__device__ __forceinline__ void mma_fp16(float* c, const unsigned* a,
                                         unsigned b0, unsigned b1) {
    asm volatile(
        "mma.sync.aligned.m16n8k16.row.col.f32.f16.f16.f32 "
        "{%0,%1,%2,%3},{%4,%5,%6,%7},{%8,%9},{%0,%1,%2,%3};"
        : "+f"(c[0]), "+f"(c[1]), "+f"(c[2]), "+f"(c[3])
        : "r"(a[0]), "r"(a[1]), "r"(a[2]), "r"(a[3]), "r"(b0), "r"(b1));
}
/* fire-and-forget release arrive */
__device__ __forceinline__ void red_release_add(unsigned* p) {
    asm volatile("red.release.gpu.global.add.u32 [%0], 1;" :: "l"(p) : "memory");
}
__device__ __forceinline__ unsigned ld_acquire(const unsigned* p) {
    unsigned v;
    asm volatile("ld.acquire.gpu.global.u32 %0, [%1];" : "=r"(v) : "l"(p) : "memory");
    return v;
}
/* overflow-free fast tanh */
__device__ __forceinline__ float fast_tanh(float x) {
    float e = __expf(-2.0f * fabsf(x));
    float r = __fdividef(1.0f - e, 1.0f + e);
    return copysignf(r, x);
}
__device__ __forceinline__ unsigned pack_h2(float lo, float hi) {
    __half2 p = __floats2half2_rn(lo, hi);
    return *(unsigned*)&p;
}

/* ===================== block-wide sum reduce ============================= */
__device__ __forceinline__ float blk_sum(float x, float* red, int tid) {
    #pragma unroll
    for (int o = 16; o; o >>= 1) x += __shfl_xor_sync(0xffffffffu, x, o);
    if ((tid & 31) == 0) red[tid >> 5] = x;
    __syncthreads();
    if (tid < 32) {
        float r = (tid < (int)(blockDim.x >> 5)) ? red[tid] : 0.f;
        #pragma unroll
        for (int o = 16; o; o >>= 1) r += __shfl_xor_sync(0xffffffffu, r, o);
        if (tid == 0) red[0] = r;
    }
    __syncthreads();
    float r = red[0];
    __syncthreads();
    return r;
}

/* ============= spectral normalization pipeline (R3-validated) ============ */
struct P1024 { float v[1024]; };

__global__ void write_u_kernel(P1024 a) {
    g_u[threadIdx.x] = a.v[threadIdx.x];
}

__global__ void norm_u_kernel() {   /* u /= ||u||  (no eps: matches ref init) */
    __shared__ float red[32];
    int tid = threadIdx.x;
    float x = g_u[tid];
    float n = sqrtf(blk_sum(x * x, red, tid));
    g_u[tid] = x / n;
}

/* v_part[bk][j] = sum_{k in slab} W[k][j] * u[k]   (grid 16, block 1024) */
__global__ void matvecT_kernel(const float* __restrict__ Wh) {
    __shared__ float us[64];
    int j = threadIdx.x, k0 = blockIdx.x * 64;
    if (j < 64) us[j] = g_u[k0 + j];
    __syncthreads();
    float s = 0.f;
    #pragma unroll 8
    for (int k = 0; k < 64; k++) s = fmaf(Wh[(size_t)(k0 + k) * DD + j], us[k], s);
    g_part[blockIdx.x][j] = s;
}

__global__ void vnorm_kernel() {    /* v = reduce(part); v /= (||v||+eps) */
    __shared__ float red[32];
    int tid = threadIdx.x;
    float v = 0.f;
    #pragma unroll
    for (int i = 0; i < 16; i++) v += g_part[i][tid];
    float n = sqrtf(blk_sum(v * v, red, tid)) + 1e-8f;
    g_v[tid] = v / n;
}

/* u_raw[r] = W[r,:] . v    (grid 32, block 256, warp handles 4 rows) */
__global__ void matvec_kernel(const float* __restrict__ Wh) {
    int lane = threadIdx.x & 31, wid = threadIdx.x >> 5;
    const float4* W4 = (const float4*)Wh;
    const float4* v4 = (const float4*)g_v;
    #pragma unroll
    for (int rr = 0; rr < 4; rr++) {
        int r = blockIdx.x * 32 + wid * 4 + rr;
        float p = 0.f;
        #pragma unroll
        for (int it = 0; it < 8; it++) {
            float4 w = W4[(size_t)r * 256 + it * 32 + lane];
            float4 v = v4[it * 32 + lane];
            p = fmaf(w.x, v.x, p); p = fmaf(w.y, v.y, p);
            p = fmaf(w.z, v.z, p); p = fmaf(w.w, v.w, p);
        }
        #pragma unroll
        for (int o = 16; o; o >>= 1) p += __shfl_xor_sync(0xffffffffu, p, o);
        if (lane == 0) g_u[r] = p;
    }
}

__global__ void unorm_kernel(int final_it) {  /* u /= (||u||+eps); maybe sigma */
    __shared__ float red[32];
    int tid = threadIdx.x;
    float x = g_u[tid];
    float n = sqrtf(blk_sum(x * x, red, tid));
    g_u[tid] = x / (n + 1e-8f);
    if (final_it && tid == 0) {
        /* sigma = u.(Wv) = ||Wv||^2/(||Wv||+eps) since u = Wv/(||Wv||+eps) */
        float sig = n * n / (n + 1e-8f);
        g_scale = 0.99f / (sig + 1e-8f);
    }
}

/* =========== prep: W16 = fp16(scale * W_h), after spectral =============== */
__global__ void prep_w16_kernel(const float* __restrict__ Wh) {
    int i = blockIdx.x * 1024 + threadIdx.x;
    g_Wh16[i] = __float2half_rn(g_scale * Wh[i]);
}

/* ============================ init / reset =============================== */
__global__ void init_kernel(const float* __restrict__ h0, float* __restrict__ out_h) {
    int i = blockIdx.x * blockDim.x + threadIdx.x;
    if (i < BD) {
        float v = h0[i];
        out_h[i] = v;
        g_h16[i] = __float2half_rn(v);
    }
    if (i < GRP) g_cnt4[i * 32] = 0u;
}
__global__ void reset_kernel() {
    int i = threadIdx.x;
    if (i < GRP) g_cnt4[i * 32] = 0u;
}

/* ===================== fp16 tensor-core GEMM ============================= */
/* C[M,N] = A[M,K]*B[N,K]^T, 128x128 tile, 8 warps, mma.m16n8k16.           */
/* Grid: blockIdx.x = n (8), blockIdx.y = m (256) for A-tile L2 reuse.      */
/* MODE 0: A = Ag_ fp32 (convert in-kernel); g_A = acc + bias[n]            */
/* MODE 1: A = g_h16+BD fp16 (device symbol); Cg = Hg * sigmoid(Zg + acc)   */
template <int MODE>
__global__ void __launch_bounds__(256, 2)
gemm16_kernel(const float* __restrict__ Ag_, const float* __restrict__ Bg,
              float* __restrict__ Cg, const float* __restrict__ bias,
              const float* __restrict__ Zg, const float* __restrict__ Hg,
              int m_off) {
    __shared__ unsigned As[128][20];
    __shared__ unsigned Bs[128][20];
    int tid = threadIdx.x, lane = tid & 31, wid = tid >> 5;
    int gr = lane >> 2, t4 = lane & 3;
    int wm = wid >> 1, wn = wid & 1;
    int n0 = blockIdx.x * 128, m0 = m_off + blockIdx.y * 128;
    const float*  Af = Ag_;
    const __half* Ah = g_h16 + BD;    /* MODE 1: h[1..T] fp16 shadow */

    float acc[2][8][4];
    #pragma unroll
    for (int mt = 0; mt < 2; mt++)
        #pragma unroll
        for (int nt = 0; nt < 8; nt++)
            #pragma unroll
            for (int i = 0; i < 4; i++) acc[mt][nt][i] = 0.f;

    float4 abuf[4]; uint4 abuf16[2]; float4 bbuf[4];
    if (MODE == 0) {
        #pragma unroll
        for (int f = 0; f < 4; f++) {
            int q = f * 256 + tid, row = q >> 3, c4 = q & 7;
            abuf[f] = *(const float4*)&Af[(size_t)(m0 + row) * DD + c4 * 4];
        }
    } else {
        #pragma unroll
        for (int f = 0; f < 2; f++) {
            int q = f * 256 + tid, row = q >> 2, c8 = q & 3;
            abuf16[f] = *(const uint4*)(Ah + (size_t)(m0 + row) * DD + c8 * 8);
        }
    }
    #pragma unroll
    for (int f = 0; f < 4; f++) {
        int q = f * 256 + tid, row = q >> 3, c4 = q & 7;
        bbuf[f] = *(const float4*)&Bg[(size_t)(n0 + row) * DD + c4 * 4];
    }

    for (int c = 0; c < 32; c++) {
        if (MODE == 0) {
            #pragma unroll
            for (int f = 0; f < 4; f++) {
                int q = f * 256 + tid, row = q >> 3, c4 = q & 7;
                *(uint2*)&As[row][c4 * 2] =
                    make_uint2(pack_h2(abuf[f].x, abuf[f].y),
                               pack_h2(abuf[f].z, abuf[f].w));
            }
        } else {
            #pragma unroll
            for (int f = 0; f < 2; f++) {
                int q = f * 256 + tid, row = q >> 2, c8 = q & 3;
                *(uint4*)&As[row][c8 * 4] = abuf16[f];
            }
        }
        #pragma unroll
        for (int f = 0; f < 4; f++) {
            int q = f * 256 + tid, row = q >> 3, c4 = q & 7;
            *(uint2*)&Bs[row][c4 * 2] =
                make_uint2(pack_h2(bbuf[f].x, bbuf[f].y),
                           pack_h2(bbuf[f].z, bbuf[f].w));
        }
        __syncthreads();
        if (c < 31) {
            int k0 = (c + 1) * 32;
            if (MODE == 0) {
                #pragma unroll
                for (int f = 0; f < 4; f++) {
                    int q = f * 256 + tid, row = q >> 3, c4 = q & 7;
                    abuf[f] = *(const float4*)&Af[(size_t)(m0 + row) * DD + k0 + c4 * 4];
                }
            } else {
                #pragma unroll
                for (int f = 0; f < 2; f++) {
                    int q = f * 256 + tid, row = q >> 2, c8 = q & 3;
                    abuf16[f] = *(const uint4*)(Ah + (size_t)(m0 + row) * DD + k0 + c8 * 8);
                }
            }
            #pragma unroll
            for (int f = 0; f < 4; f++) {
                int q = f * 256 + tid, row = q >> 3, c4 = q & 7;
                bbuf[f] = *(const float4*)&Bg[(size_t)(n0 + row) * DD + k0 + c4 * 4];
            }
        }
        #pragma unroll
        for (int ks = 0; ks < 2; ks++) {
            int aw = t4 + ks * 8;
            unsigned a[2][4];
            #pragma unroll
            for (int mt = 0; mt < 2; mt++) {
                int r = wm * 32 + mt * 16 + gr;
                a[mt][0] = As[r][aw];
                a[mt][1] = As[r + 8][aw];
                a[mt][2] = As[r][aw + 4];
                a[mt][3] = As[r + 8][aw + 4];
            }
            #pragma unroll
            for (int nt = 0; nt < 8; nt++) {
                int nc = wn * 64 + nt * 8 + gr;
                unsigned b0 = Bs[nc][aw];
                unsigned b1 = Bs[nc][aw + 4];
                mma_fp16(acc[0][nt], a[0], b0, b1);
                mma_fp16(acc[1][nt], a[1], b0, b1);
            }
        }
        __syncthreads();
    }

    /* epilogue: float2-vectorized loads/stores */
    #pragma unroll
    for (int mt = 0; mt < 2; mt++) {
        int r = m0 + wm * 32 + mt * 16 + gr;
        #pragma unroll
        for (int nt = 0; nt < 8; nt++) {
            int cc = n0 + wn * 64 + nt * 8 + t4 * 2;
            #pragma unroll
            for (int half = 0; half < 2; half++) {
                int rr = r + half * 8;
                size_t i0 = (size_t)rr * DD + cc;
                float v0 = acc[mt][nt][half * 2 + 0];
                float v1 = acc[mt][nt][half * 2 + 1];
                if (MODE == 0) {
                    float2 bb = *(const float2*)&bias[cc];
                    *(float2*)&g_A[i0] = make_float2(v0 + bb.x, v1 + bb.y);
                } else {
                    float2 hh = *(const float2*)&Hg[i0];
                    float2 zz = *(const float2*)&Zg[i0];
                    float g0 = 1.0f / (1.0f + __expf(-(zz.x + v0)));
                    float g1 = 1.0f / (1.0f + __expf(-(zz.y + v1)));
                    *(float2*)&Cg[i0] = make_float2(hh.x * g0, hh.y * g1);
                }
            }
        }
    }
}

/* ================ persistent fp16 tensor-core scan ======================= */
/* 64 blocks x 512 thr = 4 groups x 16. Same 8KB staging (now 1 uint4 per   */
/* thread -> one LDG round on the critical path). Block: 64 rows x 4        */
/* batches; warp (rt=wid&3, kq=wid>>2): 16 rows x 256 K = 16 mma. Barrier:  */
/* 16 arrivals per group counter (half the serialization + straggler pool). */
__global__ void __launch_bounds__(512, 1)
scan_kernel(float* __restrict__ out_h) {
    __shared__ __align__(16) __half hs16[4 * 1032];   /* 4 x (1024+8) halfs */
    __shared__ float comb[4 * 4 * 4 * 17];            /* [rt][kq][b][17]    */
    int tid = threadIdx.x, lane = tid & 31, wid = tid >> 5;
    int gid = blockIdx.x >> 4;         /* group 0..3 */
    int bin = blockIdx.x & 15;         /* block within group */
    int rt  = wid & 3;                 /* row-tile 0..3 */
    int kq  = wid >> 2;                /* K-quarter 0..3 */
    int r0  = bin * 64 + rt * 16;      /* warp's 16 rows */
    int gb  = gid * 4;                 /* batch base */
    int gr = lane >> 2, t4 = lane & 3;

    /* loop-invariant A fragments: W16[16 rows x 256 K] -> 16 mma x 4 regs */
    unsigned wf[16][4];
    {
        const __half* wra = g_Wh16 + (size_t)(r0 + gr) * DD + kq * 256 + 2 * t4;
        const __half* wrb = wra + (size_t)8 * DD;
        #pragma unroll
        for (int m = 0; m < 16; m++) {
            wf[m][0] = *(const unsigned*)(wra + m * 16);
            wf[m][1] = *(const unsigned*)(wrb + m * 16);
            wf[m][2] = *(const unsigned*)(wra + m * 16 + 8);
            wf[m][3] = *(const unsigned*)(wrb + m * 16 + 8);
        }
    }

    unsigned* cnt = &g_cnt4[gid * 32];

    /* output-phase constants (threads 0..255 produce one h value each) */
    int b_o  = tid >> 6;               /* batch 0..3 (tid<256) */
    int rl   = tid & 63;               /* local row 0..63 */
    int rt_o = rl >> 4, r_o = rl & 15;
    size_t oidx = (size_t)(gb + b_o) * DD + (bin * 64 + rl);

    /* B-fragment smem word index (broadcast for lanes 16-31) */
    int n4 = gr & 3;
    const unsigned* hsw = (const unsigned*)hs16;
    int bbase = n4 * 516 + kq * 128 + t4;

    float a_val = (tid < 256) ? __ldcg(&g_A[oidx]) : 0.f;

    for (int t = 0; t < TT; t++) {
        /* stage h16 tile (4 batches x 1024 halfs = 8KB): 1 uint4/thread */
        {
            const __half* hsrc = g_h16 + (size_t)t * BD + (size_t)gb * DD;
            uint4 v0 = *(const uint4*)(hsrc + (tid >> 7) * DD + (tid & 127) * 8);
            *(uint4*)(hs16 + (tid >> 7) * 1032 + (tid & 127) * 8) = v0;
        }
        __syncthreads();

        /* prefetch next step's additive term */
        float a_next = 0.f;
        if (t + 1 < TT && tid < 256)
            a_next = __ldcg(&g_A[(size_t)(t + 1) * BD + oidx]);

        /* 16 mma, two independent accumulator chains */
        float ce[4] = {0.f, 0.f, 0.f, 0.f};
        float co[4] = {0.f, 0.f, 0.f, 0.f};
        #pragma unroll
        for (int m = 0; m < 16; m += 2) {
            unsigned b0 = hsw[bbase + m * 8];
            unsigned b1 = hsw[bbase + m * 8 + 4];
            mma_fp16(ce, wf[m], b0, b1);
            unsigned b2 = hsw[bbase + (m + 1) * 8];
            unsigned b3 = hsw[bbase + (m + 1) * 8 + 4];
            mma_fp16(co, wf[m + 1], b2, b3);
        }

        /* write valid fragment lanes to comb: rows gr, gr+8; cols 2t4,2t4+1 */
        if (t4 < 2) {
            int cb = (rt * 4 + kq) * 4 + 2 * t4;
            comb[(cb    ) * 17 + gr    ] = ce[0] + co[0];
            comb[(cb + 1) * 17 + gr    ] = ce[1] + co[1];
            comb[(cb    ) * 17 + gr + 8] = ce[2] + co[2];
            comb[(cb + 1) * 17 + gr + 8] = ce[3] + co[3];
        }
        __syncthreads();

        /* output: sum 4 K-quarters, tanh, fp16 shadow store pre-release */
        float hv = 0.f;
        if (tid < 256) {
            float tot = comb[((rt_o * 4 + 0) * 4 + b_o) * 17 + r_o]
                      + comb[((rt_o * 4 + 1) * 4 + b_o) * 17 + r_o]
                      + comb[((rt_o * 4 + 2) * 4 + b_o) * 17 + r_o]
                      + comb[((rt_o * 4 + 3) * 4 + b_o) * 17 + r_o];
            hv = fast_tanh(tot + a_val);
            g_h16[(size_t)(t + 1) * BD + oidx] = __float2half_rn(hv);
        }

        /* group barrier: release-arrive + acquire-poll (R10 protocol) */
        if (t + 1 < TT) {
            __syncthreads();
            if (tid == 0) {
                red_release_add(cnt);
                unsigned target = (unsigned)(t + 1) * (unsigned)BPG;
                while (ld_acquire(cnt) < target) { }
            }
            __syncthreads();
        }

        /* deferred fp32 store — off the release critical path */
        if (tid < 256)
            out_h[(size_t)(t + 1) * BD + oidx] = hv;

        a_val = a_next;
    }
}

/* ================== host-side numpy-exact randn(1024) ==================== */
static void host_randn1024(float* out) {
    static unsigned mt[624];
    int pos;
    {
        unsigned s = 0u;
        for (int i = 0; i < 624; i++) {
            mt[i] = s;
            s = 1812433253u * (s ^ (s >> 30)) + (unsigned)(i + 1);
        }
        pos = 624;
    }
    auto next = [&]() -> unsigned {
        if (pos == 624) {
            for (int i = 0; i < 624; i++) {
                unsigned y = (mt[i] & 0x80000000u) | (mt[(i + 1) % 624] & 0x7fffffffu);
                mt[i] = mt[(i + 397) % 624] ^ (y >> 1) ^ ((y & 1u) ? 0x9908b0dfu : 0u);
            }
            pos = 0;
        }
        unsigned y = mt[pos++];
        y ^= y >> 11;
        y ^= (y << 7) & 0x9d2c5680u;
        y ^= (y << 15) & 0xefc60000u;
        y ^= y >> 18;
        return y;
    };
    auto nextDouble = [&]() -> double {
        unsigned a = next() >> 5, b = next() >> 6;
        return ((double)a * 67108864.0 + (double)b) / 9007199254740992.0;
    };
    bool has_g = false;
    double gcache = 0.0;
    for (int i = 0; i < DD; i++) {
        double val;
        if (has_g) { val = gcache; has_g = false; }
        else {
            double x1, x2, r2;
            do {
                x1 = 2.0 * nextDouble() - 1.0;
                x2 = 2.0 * nextDouble() - 1.0;
                r2 = x1 * x1 + x2 * x2;
            } while (r2 >= 1.0 || r2 == 0.0);
            double f = sqrt(-2.0 * log(r2) / r2);
            gcache = f * x1; has_g = true; val = f * x2;
        }
        out[i] = (float)val;
    }
}

/* ============================== launcher ================================= */
extern "C" void kernel_launch(void* const* d_in, const int* in_sizes, int n_in,
                              void* d_out, int out_size) {
    const float* x    = (const float*)d_in[0];
    const float* z    = (const float*)d_in[1];
    const float* h0   = (const float*)d_in[2];
    const float* Wx   = (const float*)d_in[3];
    const float* Wh   = (const float*)d_in[4];
    const float* Wg   = (const float*)d_in[5];
    const float* bias = (const float*)d_in[6];

    float* out   = (float*)d_out;
    float* outs  = out;                          /* [T, B, D]   */
    float* out_h = out + (size_t)NROW * DD;      /* [T+1, B, D] */
    const float* hs = out_h + BD;                /* h[1..T], row = t*B+b */

    static float u_host[DD];
    host_randn1024(u_host);
    P1024 u0;
    for (int i = 0; i < DD; i++) u0.v[i] = u_host[i];

    /* multi-block spectral pipeline (R3-validated) */
    write_u_kernel<<<1, 1024>>>(u0);
    norm_u_kernel<<<1, 1024>>>();
    for (int it = 0; it < 3; it++) {
        matvecT_kernel<<<16, 1024>>>(Wh);
        vnorm_kernel<<<1, 1024>>>();
        matvec_kernel<<<32, 256>>>(Wh);
        unorm_kernel<<<1, 1024>>>(it == 2 ? 1 : 0);
    }
    prep_w16_kernel<<<1024, 1024>>>(Wh);

    init_kernel<<<16, 1024>>>(h0, out_h);
    gemm16_kernel<0><<<dim3(8, 256), 256>>>(x, Wx, nullptr, bias,
                                            nullptr, nullptr, 0);
    reset_kernel<<<1, 32>>>();
    scan_kernel<<<SNB, 512>>>(out_h);
    gemm16_kernel<1><<<dim3(8, 256), 256>>>(nullptr, Wg, outs, nullptr,
                                            z, hs, 0);
}

// round 17
// speedup vs baseline: 1.1241x; 1.1241x over previous
#include <cuda_runtime.h>
#include <cuda_fp16.h>
#include <math.h>

#define DD   1024
#define BB   16
#define TT   2048
#define NROW (TT*BB)          /* 32768 */
#define BD   (BB*DD)          /* 16384 */
#define SNB  128              /* scan blocks total */
#define GRP  4                /* independent batch groups (4 batches each) */
#define BPG  32               /* blocks per group */

/* ------------- static device scratch (no allocations allowed) ------------- */
__device__ float    g_A[33554432];            /* x@Wx^T + b, [T*B, D], 128MB */
__device__ float    g_scale;                  /* 0.99/(sigma+eps) */
__device__ unsigned g_cnt4[GRP * 32];         /* one 128B line per group */
__device__ __half   g_Wh16[DD * DD];          /* fp16 of (scale * W_h), 2MB */
__device__ __half   g_h16[(TT + 1) * BD];     /* fp16 shadow of h, 67MB */
__device__ float    g_u[DD];
__device__ float    g_v[DD];
__device__ float    g_part[16][DD];

/* ====================== small PTX helpers ================================ */
__device__ __forceinline__ void mma_fp16(float* c, const unsigned* a,
                                         unsigned b0, unsigned b1) {
    asm volatile(
        "mma.sync.aligned.m16n8k16.row.col.f32.f16.f16.f32 "
        "{%0,%1,%2,%3},{%4,%5,%6,%7},{%8,%9},{%0,%1,%2,%3};"
        : "+f"(c[0]), "+f"(c[1]), "+f"(c[2]), "+f"(c[3])
        : "r"(a[0]), "r"(a[1]), "r"(a[2]), "r"(a[3]), "r"(b0), "r"(b1));
}
/* fire-and-forget release arrive */
__device__ __forceinline__ void red_release_add(unsigned* p) {
    asm volatile("red.release.gpu.global.add.u32 [%0], 1;" :: "l"(p) : "memory");
}
__device__ __forceinline__ unsigned ld_acquire(const unsigned* p) {
    unsigned v;
    asm volatile("ld.acquire.gpu.global.u32 %0, [%1];" : "=r"(v) : "l"(p) : "memory");
    return v;
}
/* overflow-free fast tanh */
__device__ __forceinline__ float fast_tanh(float x) {
    float e = __expf(-2.0f * fabsf(x));
    float r = __fdividef(1.0f - e, 1.0f + e);
    return copysignf(r, x);
}
__device__ __forceinline__ unsigned pack_h2(float lo, float hi) {
    __half2 p = __floats2half2_rn(lo, hi);
    return *(unsigned*)&p;
}

/* ===================== block-wide sum reduce ============================= */
__device__ __forceinline__ float blk_sum(float x, float* red, int tid) {
    #pragma unroll
    for (int o = 16; o; o >>= 1) x += __shfl_xor_sync(0xffffffffu, x, o);
    if ((tid & 31) == 0) red[tid >> 5] = x;
    __syncthreads();
    if (tid < 32) {
        float r = (tid < (int)(blockDim.x >> 5)) ? red[tid] : 0.f;
        #pragma unroll
        for (int o = 16; o; o >>= 1) r += __shfl_xor_sync(0xffffffffu, r, o);
        if (tid == 0) red[0] = r;
    }
    __syncthreads();
    float r = red[0];
    __syncthreads();
    return r;
}

/* ============= spectral normalization pipeline (R3-validated) ============ */
struct P1024 { float v[1024]; };

__global__ void write_u_kernel(P1024 a) {
    g_u[threadIdx.x] = a.v[threadIdx.x];
}

__global__ void norm_u_kernel() {   /* u /= ||u||  (no eps: matches ref init) */
    __shared__ float red[32];
    int tid = threadIdx.x;
    float x = g_u[tid];
    float n = sqrtf(blk_sum(x * x, red, tid));
    g_u[tid] = x / n;
}

/* v_part[bk][j] = sum_{k in slab} W[k][j] * u[k]   (grid 16, block 1024) */
__global__ void matvecT_kernel(const float* __restrict__ Wh) {
    __shared__ float us[64];
    int j = threadIdx.x, k0 = blockIdx.x * 64;
    if (j < 64) us[j] = g_u[k0 + j];
    __syncthreads();
    float s = 0.f;
    #pragma unroll 8
    for (int k = 0; k < 64; k++) s = fmaf(Wh[(size_t)(k0 + k) * DD + j], us[k], s);
    g_part[blockIdx.x][j] = s;
}

__global__ void vnorm_kernel() {    /* v = reduce(part); v /= (||v||+eps) */
    __shared__ float red[32];
    int tid = threadIdx.x;
    float v = 0.f;
    #pragma unroll
    for (int i = 0; i < 16; i++) v += g_part[i][tid];
    float n = sqrtf(blk_sum(v * v, red, tid)) + 1e-8f;
    g_v[tid] = v / n;
}

/* u_raw[r] = W[r,:] . v    (grid 32, block 256, warp handles 4 rows) */
__global__ void matvec_kernel(const float* __restrict__ Wh) {
    int lane = threadIdx.x & 31, wid = threadIdx.x >> 5;
    const float4* W4 = (const float4*)Wh;
    const float4* v4 = (const float4*)g_v;
    #pragma unroll
    for (int rr = 0; rr < 4; rr++) {
        int r = blockIdx.x * 32 + wid * 4 + rr;
        float p = 0.f;
        #pragma unroll
        for (int it = 0; it < 8; it++) {
            float4 w = W4[(size_t)r * 256 + it * 32 + lane];
            float4 v = v4[it * 32 + lane];
            p = fmaf(w.x, v.x, p); p = fmaf(w.y, v.y, p);
            p = fmaf(w.z, v.z, p); p = fmaf(w.w, v.w, p);
        }
        #pragma unroll
        for (int o = 16; o; o >>= 1) p += __shfl_xor_sync(0xffffffffu, p, o);
        if (lane == 0) g_u[r] = p;
    }
}

__global__ void unorm_kernel(int final_it) {  /* u /= (||u||+eps); maybe sigma */
    __shared__ float red[32];
    int tid = threadIdx.x;
    float x = g_u[tid];
    float n = sqrtf(blk_sum(x * x, red, tid));
    g_u[tid] = x / (n + 1e-8f);
    if (final_it && tid == 0) {
        /* sigma = u.(Wv) = ||Wv||^2/(||Wv||+eps) since u = Wv/(||Wv||+eps) */
        float sig = n * n / (n + 1e-8f);
        g_scale = 0.99f / (sig + 1e-8f);
    }
}

/* =========== prep: W16 = fp16(scale * W_h), after spectral =============== */
__global__ void prep_w16_kernel(const float* __restrict__ Wh) {
    int i = blockIdx.x * 1024 + threadIdx.x;
    g_Wh16[i] = __float2half_rn(g_scale * Wh[i]);
}

/* ============================ init / reset =============================== */
__global__ void init_kernel(const float* __restrict__ h0, float* __restrict__ out_h) {
    int i = blockIdx.x * blockDim.x + threadIdx.x;
    if (i < BD) {
        float v = h0[i];
        out_h[i] = v;
        g_h16[i] = __float2half_rn(v);
    }
    if (i < GRP) g_cnt4[i * 32] = 0u;
}
__global__ void reset_kernel() {
    int i = threadIdx.x;
    if (i < GRP) g_cnt4[i * 32] = 0u;
}

/* ===================== fp16 tensor-core GEMM ============================= */
/* C[M,N] = A[M,K]*B[N,K]^T, 128x128 tile, 8 warps, mma.m16n8k16.           */
/* Grid: blockIdx.x = n (8), blockIdx.y = m (256) for A-tile L2 reuse.      */
/* MODE 0: A = Ag_ fp32 (convert in-kernel); g_A = acc + bias[n]            */
/* MODE 1: A = g_h16+BD fp16 (device symbol); Cg = h16 * sigmoid(Zg + acc)  */
/*         (h for the product read from the fp16 shadow = same rows the     */
/*          kernel already streams as A -> L2 hits, no fp32 Hg traffic)     */
template <int MODE>
__global__ void __launch_bounds__(256, 2)
gemm16_kernel(const float* __restrict__ Ag_, const float* __restrict__ Bg,
              float* __restrict__ Cg, const float* __restrict__ bias,
              const float* __restrict__ Zg,
              int m_off) {
    __shared__ unsigned As[128][20];
    __shared__ unsigned Bs[128][20];
    int tid = threadIdx.x, lane = tid & 31, wid = tid >> 5;
    int gr = lane >> 2, t4 = lane & 3;
    int wm = wid >> 1, wn = wid & 1;
    int n0 = blockIdx.x * 128, m0 = m_off + blockIdx.y * 128;
    const float*  Af = Ag_;
    const __half* Ah = g_h16 + BD;    /* MODE 1: h[1..T] fp16 shadow */

    float acc[2][8][4];
    #pragma unroll
    for (int mt = 0; mt < 2; mt++)
        #pragma unroll
        for (int nt = 0; nt < 8; nt++)
            #pragma unroll
            for (int i = 0; i < 4; i++) acc[mt][nt][i] = 0.f;

    float4 abuf[4]; uint4 abuf16[2]; float4 bbuf[4];
    if (MODE == 0) {
        #pragma unroll
        for (int f = 0; f < 4; f++) {
            int q = f * 256 + tid, row = q >> 3, c4 = q & 7;
            abuf[f] = *(const float4*)&Af[(size_t)(m0 + row) * DD + c4 * 4];
        }
    } else {
        #pragma unroll
        for (int f = 0; f < 2; f++) {
            int q = f * 256 + tid, row = q >> 2, c8 = q & 3;
            abuf16[f] = *(const uint4*)(Ah + (size_t)(m0 + row) * DD + c8 * 8);
        }
    }
    #pragma unroll
    for (int f = 0; f < 4; f++) {
        int q = f * 256 + tid, row = q >> 3, c4 = q & 7;
        bbuf[f] = *(const float4*)&Bg[(size_t)(n0 + row) * DD + c4 * 4];
    }

    for (int c = 0; c < 32; c++) {
        if (MODE == 0) {
            #pragma unroll
            for (int f = 0; f < 4; f++) {
                int q = f * 256 + tid, row = q >> 3, c4 = q & 7;
                *(uint2*)&As[row][c4 * 2] =
                    make_uint2(pack_h2(abuf[f].x, abuf[f].y),
                               pack_h2(abuf[f].z, abuf[f].w));
            }
        } else {
            #pragma unroll
            for (int f = 0; f < 2; f++) {
                int q = f * 256 + tid, row = q >> 2, c8 = q & 3;
                *(uint4*)&As[row][c8 * 4] = abuf16[f];
            }
        }
        #pragma unroll
        for (int f = 0; f < 4; f++) {
            int q = f * 256 + tid, row = q >> 3, c4 = q & 7;
            *(uint2*)&Bs[row][c4 * 2] =
                make_uint2(pack_h2(bbuf[f].x, bbuf[f].y),
                           pack_h2(bbuf[f].z, bbuf[f].w));
        }
        __syncthreads();
        if (c < 31) {
            int k0 = (c + 1) * 32;
            if (MODE == 0) {
                #pragma unroll
                for (int f = 0; f < 4; f++) {
                    int q = f * 256 + tid, row = q >> 3, c4 = q & 7;
                    abuf[f] = *(const float4*)&Af[(size_t)(m0 + row) * DD + k0 + c4 * 4];
                }
            } else {
                #pragma unroll
                for (int f = 0; f < 2; f++) {
                    int q = f * 256 + tid, row = q >> 2, c8 = q & 3;
                    abuf16[f] = *(const uint4*)(Ah + (size_t)(m0 + row) * DD + k0 + c8 * 8);
                }
            }
            #pragma unroll
            for (int f = 0; f < 4; f++) {
                int q = f * 256 + tid, row = q >> 3, c4 = q & 7;
                bbuf[f] = *(const float4*)&Bg[(size_t)(n0 + row) * DD + k0 + c4 * 4];
            }
        }
        #pragma unroll
        for (int ks = 0; ks < 2; ks++) {
            int aw = t4 + ks * 8;
            unsigned a[2][4];
            #pragma unroll
            for (int mt = 0; mt < 2; mt++) {
                int r = wm * 32 + mt * 16 + gr;
                a[mt][0] = As[r][aw];
                a[mt][1] = As[r + 8][aw];
                a[mt][2] = As[r][aw + 4];
                a[mt][3] = As[r + 8][aw + 4];
            }
            #pragma unroll
            for (int nt = 0; nt < 8; nt++) {
                int nc = wn * 64 + nt * 8 + gr;
                unsigned b0 = Bs[nc][aw];
                unsigned b1 = Bs[nc][aw + 4];
                mma_fp16(acc[0][nt], a[0], b0, b1);
                mma_fp16(acc[1][nt], a[1], b0, b1);
            }
        }
        __syncthreads();
    }

    /* epilogue: float2-vectorized; MODE 1 h from fp16 shadow (L2-hot) */
    #pragma unroll
    for (int mt = 0; mt < 2; mt++) {
        int r = m0 + wm * 32 + mt * 16 + gr;
        #pragma unroll
        for (int nt = 0; nt < 8; nt++) {
            int cc = n0 + wn * 64 + nt * 8 + t4 * 2;
            #pragma unroll
            for (int half = 0; half < 2; half++) {
                int rr = r + half * 8;
                size_t i0 = (size_t)rr * DD + cc;
                float v0 = acc[mt][nt][half * 2 + 0];
                float v1 = acc[mt][nt][half * 2 + 1];
                if (MODE == 0) {
                    float2 bb = *(const float2*)&bias[cc];
                    *(float2*)&g_A[i0] = make_float2(v0 + bb.x, v1 + bb.y);
                } else {
                    __half2 hh16 = *(const __half2*)(Ah + i0);
                    float2 hh = __half22float2(hh16);
                    float2 zz = *(const float2*)&Zg[i0];
                    float g0 = 1.0f / (1.0f + __expf(-(zz.x + v0)));
                    float g1 = 1.0f / (1.0f + __expf(-(zz.y + v1)));
                    *(float2*)&Cg[i0] = make_float2(hh.x * g0, hh.y * g1);
                }
            }
        }
    }
}

/* ================ persistent fp16 tensor-core scan ======================= */
/* FROZEN R10/R15 configuration (measured optimum across 4 counter-         */
/* experiments): 128 blocks = 4 groups x 32, 4 batches/group, 8KB staging,  */
/* single counter per group, release-arrive + single-thread acquire-poll,   */
/* deferred fp32 store.                                                     */
__global__ void __launch_bounds__(256, 1)
scan_kernel(float* __restrict__ out_h) {
    __shared__ __align__(16) __half hs16[4 * 1032];   /* 4 x (1024+8) halfs */
    __shared__ float comb[2 * 4 * 4 * 17];            /* [rt][kq][b][17]    */
    int tid = threadIdx.x, lane = tid & 31, wid = tid >> 5;
    int gid = blockIdx.x >> 5;         /* group 0..3 */
    int bin = blockIdx.x & 31;         /* block within group */
    int rt  = wid & 1;                 /* row-tile 0/1 */
    int kq  = wid >> 1;                /* K-quarter 0..3 */
    int r0  = bin * 32 + rt * 16;      /* warp's 16 rows */
    int gb  = gid * 4;                 /* batch base */
    int gr = lane >> 2, t4 = lane & 3;

    /* loop-invariant A fragments: W16[16 rows x 256 K] -> 16 mma x 4 regs */
    unsigned wf[16][4];
    {
        const __half* wra = g_Wh16 + (size_t)(r0 + gr) * DD + kq * 256 + 2 * t4;
        const __half* wrb = wra + (size_t)8 * DD;
        #pragma unroll
        for (int m = 0; m < 16; m++) {
            wf[m][0] = *(const unsigned*)(wra + m * 16);
            wf[m][1] = *(const unsigned*)(wrb + m * 16);
            wf[m][2] = *(const unsigned*)(wra + m * 16 + 8);
            wf[m][3] = *(const unsigned*)(wrb + m * 16 + 8);
        }
    }

    unsigned* cnt = &g_cnt4[gid * 32];

    /* output-phase constants (threads 0..127 produce one h value each) */
    int b_o  = tid >> 5;               /* batch 0..3 (tid<128) */
    int rl   = tid & 31;               /* local row 0..31 */
    int rt_o = rl >> 4, r_o = rl & 15;
    size_t oidx = (size_t)(gb + b_o) * DD + (bin * 32 + rl);

    /* B-fragment smem word index (broadcast for lanes 16-31) */
    int n4 = gr & 3;
    const unsigned* hsw = (const unsigned*)hs16;
    int bbase = n4 * 516 + kq * 128 + t4;

    float a_val = (tid < 128) ? __ldcg(&g_A[oidx]) : 0.f;

    for (int t = 0; t < TT; t++) {
        /* stage h16 tile (4 batches x 1024 halfs = 8KB) into smem */
        {
            const __half* hsrc = g_h16 + (size_t)t * BD + (size_t)gb * DD;
            int c0 = tid, c1 = tid + 256;
            uint4 v0 = *(const uint4*)(hsrc + (c0 >> 7) * DD + (c0 & 127) * 8);
            uint4 v1 = *(const uint4*)(hsrc + (c1 >> 7) * DD + (c1 & 127) * 8);
            *(uint4*)(hs16 + (c0 >> 7) * 1032 + (c0 & 127) * 8) = v0;
            *(uint4*)(hs16 + (c1 >> 7) * 1032 + (c1 & 127) * 8) = v1;
        }
        __syncthreads();

        /* prefetch next step's additive term */
        float a_next = 0.f;
        if (t + 1 < TT && tid < 128)
            a_next = __ldcg(&g_A[(size_t)(t + 1) * BD + oidx]);

        /* 16 mma, two independent accumulator chains */
        float ce[4] = {0.f, 0.f, 0.f, 0.f};
        float co[4] = {0.f, 0.f, 0.f, 0.f};
        #pragma unroll
        for (int m = 0; m < 16; m += 2) {
            unsigned b0 = hsw[bbase + m * 8];
            unsigned b1 = hsw[bbase + m * 8 + 4];
            mma_fp16(ce, wf[m], b0, b1);
            unsigned b2 = hsw[bbase + (m + 1) * 8];
            unsigned b3 = hsw[bbase + (m + 1) * 8 + 4];
            mma_fp16(co, wf[m + 1], b2, b3);
        }

        /* write valid fragment lanes to comb: rows gr, gr+8; cols 2t4,2t4+1 */
        if (t4 < 2) {
            int cb = (rt * 4 + kq) * 4 + 2 * t4;
            comb[(cb    ) * 17 + gr    ] = ce[0] + co[0];
            comb[(cb + 1) * 17 + gr    ] = ce[1] + co[1];
            comb[(cb    ) * 17 + gr + 8] = ce[2] + co[2];
            comb[(cb + 1) * 17 + gr + 8] = ce[3] + co[3];
        }
        __syncthreads();

        /* output: sum 4 K-quarters, tanh, fp16 shadow store pre-release */
        float hv = 0.f;
        if (tid < 128) {
            float tot = comb[((rt_o * 4 + 0) * 4 + b_o) * 17 + r_o]
                      + comb[((rt_o * 4 + 1) * 4 + b_o) * 17 + r_o]
                      + comb[((rt_o * 4 + 2) * 4 + b_o) * 17 + r_o]
                      + comb[((rt_o * 4 + 3) * 4 + b_o) * 17 + r_o];
            hv = fast_tanh(tot + a_val);
            g_h16[(size_t)(t + 1) * BD + oidx] = __float2half_rn(hv);
        }

        /* group barrier: release-arrive + acquire-poll (R10 protocol) */
        if (t + 1 < TT) {
            __syncthreads();
            if (tid == 0) {
                red_release_add(cnt);
                unsigned target = (unsigned)(t + 1) * (unsigned)BPG;
                while (ld_acquire(cnt) < target) { }
            }
            __syncthreads();
        }

        /* deferred fp32 store — off the release critical path */
        if (tid < 128)
            out_h[(size_t)(t + 1) * BD + oidx] = hv;

        a_val = a_next;
    }
}

/* ================== host-side numpy-exact randn(1024) ==================== */
static void host_randn1024(float* out) {
    static unsigned mt[624];
    int pos;
    {
        unsigned s = 0u;
        for (int i = 0; i < 624; i++) {
            mt[i] = s;
            s = 1812433253u * (s ^ (s >> 30)) + (unsigned)(i + 1);
        }
        pos = 624;
    }
    auto next = [&]() -> unsigned {
        if (pos == 624) {
            for (int i = 0; i < 624; i++) {
                unsigned y = (mt[i] & 0x80000000u) | (mt[(i + 1) % 624] & 0x7fffffffu);
                mt[i] = mt[(i + 397) % 624] ^ (y >> 1) ^ ((y & 1u) ? 0x9908b0dfu : 0u);
            }
            pos = 0;
        }
        unsigned y = mt[pos++];
        y ^= y >> 11;
        y ^= (y << 7) & 0x9d2c5680u;
        y ^= (y << 15) & 0xefc60000u;
        y ^= y >> 18;
        return y;
    };
    auto nextDouble = [&]() -> double {
        unsigned a = next() >> 5, b = next() >> 6;
        return ((double)a * 67108864.0 + (double)b) / 9007199254740992.0;
    };
    bool has_g = false;
    double gcache = 0.0;
    for (int i = 0; i < DD; i++) {
        double val;
        if (has_g) { val = gcache; has_g = false; }
        else {
            double x1, x2, r2;
            do {
                x1 = 2.0 * nextDouble() - 1.0;
                x2 = 2.0 * nextDouble() - 1.0;
                r2 = x1 * x1 + x2 * x2;
            } while (r2 >= 1.0 || r2 == 0.0);
            double f = sqrt(-2.0 * log(r2) / r2);
            gcache = f * x1; has_g = true; val = f * x2;
        }
        out[i] = (float)val;
    }
}

/* ============================== launcher ================================= */
extern "C" void kernel_launch(void* const* d_in, const int* in_sizes, int n_in,
                              void* d_out, int out_size) {
    const float* x    = (const float*)d_in[0];
    const float* z    = (const float*)d_in[1];
    const float* h0   = (const float*)d_in[2];
    const float* Wx   = (const float*)d_in[3];
    const float* Wh   = (const float*)d_in[4];
    const float* Wg   = (const float*)d_in[5];
    const float* bias = (const float*)d_in[6];

    float* out   = (float*)d_out;
    float* outs  = out;                          /* [T, B, D]   */
    float* out_h = out + (size_t)NROW * DD;      /* [T+1, B, D] */

    static float u_host[DD];
    host_randn1024(u_host);
    P1024 u0;
    for (int i = 0; i < DD; i++) u0.v[i] = u_host[i];

    /* multi-block spectral pipeline (R3-validated) */
    write_u_kernel<<<1, 1024>>>(u0);
    norm_u_kernel<<<1, 1024>>>();
    for (int it = 0; it < 3; it++) {
        matvecT_kernel<<<16, 1024>>>(Wh);
        vnorm_kernel<<<1, 1024>>>();
        matvec_kernel<<<32, 256>>>(Wh);
        unorm_kernel<<<1, 1024>>>(it == 2 ? 1 : 0);
    }
    prep_w16_kernel<<<1024, 1024>>>(Wh);

    init_kernel<<<16, 1024>>>(h0, out_h);
    gemm16_kernel<0><<<dim3(8, 256), 256>>>(x, Wx, nullptr, bias,
                                            nullptr, 0);
    reset_kernel<<<1, 32>>>();
    scan_kernel<<<SNB, 256>>>(out_h);
    gemm16_kernel<1><<<dim3(8, 256), 256>>>(nullptr, Wg, outs, nullptr,
                                            z, 0);
}